// round 4
// baseline (speedup 1.0000x reference)
#include <cuda_runtime.h>
#include <stdint.h>

// PointPillars BEV scatter: (M,3) coords + (M,64) features -> (B,64,496,432)
#define BEV_H   496
#define BEV_W   432
#define NB      4
#define NC      64
#define HW      (BEV_H * BEV_W)        // 214272 cells per batch image
#define NCELLS  (NB * HW)              // 857088 total grid cells
#define CELLS_PB 128                   // cells per block
#define NBLK    (NCELLS / CELLS_PB)    // 6696 blocks, exact
#define SSTRIDE 65                     // odd smem row stride (floats) -> conflict-free transpose

// Inverse map: raveled cell -> pillar index + 1 (0 = empty). 3.43 MB.
// SELF-CLEANING: zero at module load; gather zeroes each occupied entry right
// after reading it, so the map is all-zero again at the end of every call.
__device__ int g_map[NCELLS];

// ---------------------------------------------------------------------------
// Kernel 1: scatter pillar index+1 into the map (coords are collision-free).
__global__ void scatter_idx_kernel(const int* __restrict__ coords, int M) {
    int m = blockIdx.x * blockDim.x + threadIdx.x;
    if (m < M) {
        int b = coords[3 * m + 0];
        int y = coords[3 * m + 1];
        int x = coords[3 * m + 2];
        g_map[(b * BEV_H + y) * BEV_W + x] = m + 1;
    }
}

// ---------------------------------------------------------------------------
// Kernel 2: dense gather via smem transpose. Block owns 128 consecutive
// raveled cells (never straddles a batch boundary: 214272 % 128 == 0).
//  P1: coalesced map read (+ self-clean).
//  P2: 16-lane groups read pillar rows as 16 x float4 = 256 B coalesced,
//      stage to s_f[slot][c] (stride 65; STS 2-way conflict).
//  P3: warp w stores channels 8w..8w+7; lane l covers slot g*32+l.
//      LDS word = slot*65 + c -> lane-stride 65 -> conflict-free.
//      STG.32 per warp = 128 B contiguous (out plane raveled same as cells).
__global__ __launch_bounds__(256) void gather_kernel(
    const float* __restrict__ feat, float* __restrict__ out) {
    __shared__ int   s_map[CELLS_PB];
    __shared__ float s_f[CELLS_PB * SSTRIDE];   // 33,280 B

    const int t    = threadIdx.x;
    const int base = blockIdx.x * CELLS_PB;

    // Phase 1: coalesced map read + self-clean
    if (t < CELLS_PB) {
        int pid = g_map[base + t];
        s_map[t] = pid;
        if (pid) g_map[base + t] = 0;
    }
    __syncthreads();

    // Phase 2: coalesced feature-row loads into smem
    const int grp = t >> 4;   // 0..15: slot group
    const int q   = t & 15;   // channel quad within the row
#pragma unroll
    for (int it = 0; it < CELLS_PB / 16; ++it) {
        const int s   = it * 16 + grp;
        const int pid = s_map[s];
        float4 v = make_float4(0.f, 0.f, 0.f, 0.f);
        if (pid)
            v = *reinterpret_cast<const float4*>(
                    feat + (size_t)(pid - 1) * NC + 4 * q);
        float* dst = &s_f[s * SSTRIDE + 4 * q];
        dst[0] = v.x; dst[1] = v.y; dst[2] = v.z; dst[3] = v.w;
    }
    __syncthreads();

    // Phase 3: transposed, fully coalesced store
    const int b  = base / HW;            // constant per block
    const int l  = t & 31;
    const int c0 = (t >> 5) * 8;         // warp's channel base
    float* outb = out + (size_t)b * NC * HW + (base - b * HW);
#pragma unroll
    for (int g = 0; g < 4; ++g) {
        const int slot = g * 32 + l;
        const float* row = &s_f[slot * SSTRIDE];
#pragma unroll
        for (int j = 0; j < 8; ++j) {
            outb[(size_t)(c0 + j) * HW + slot] = row[c0 + j];
        }
    }
}

// ---------------------------------------------------------------------------
extern "C" void kernel_launch(void* const* d_in, const int* in_sizes, int n_in,
                              void* d_out, int out_size) {
    const int*   coords = (const int*)d_in[0];    // (M, 3) int32
    const float* feat   = (const float*)d_in[1];  // (M, 64) float32
    float*       out    = (float*)d_out;          // (4, 64, 496, 432) float32
    const int M = in_sizes[0] / 3;

    scatter_idx_kernel<<<(M + 255) / 256, 256>>>(coords, M);
    gather_kernel<<<NBLK, 256>>>(feat, out);
}

// round 5
// speedup vs baseline: 1.1262x; 1.1262x over previous
#include <cuda_runtime.h>
#include <stdint.h>

// PointPillars BEV scatter: (M,3) coords + (M,64) features -> (B,64,496,432)
#define BEV_H    496
#define BEV_W    432
#define NB       4
#define NC       64
#define HW       (BEV_H * BEV_W)       // 214272 cells per batch image
#define NCELLS   (NB * HW)             // 857088 total grid cells
#define CELLS_PB 128                   // cells per block (128 | 214272)
#define NBLK     (NCELLS / CELLS_PB)   // 6696 blocks, exact
#define SST      132                   // slot stride in floats: 16B-aligned rows

// Inverse map: raveled cell -> pillar index + 1 (0 = empty). 3.43 MB.
// SELF-CLEANING: zero at module load; gather zeroes each occupied entry after
// reading it, so the map is all-zero again at the end of every call.
__device__ int g_map[NCELLS];

// ---------------------------------------------------------------------------
// Kernel 1: scatter pillar index+1 into the map (coords are collision-free).
__global__ void scatter_idx_kernel(const int* __restrict__ coords, int M) {
    int m = blockIdx.x * blockDim.x + threadIdx.x;
    if (m < M) {
        int b = coords[3 * m + 0];
        int y = coords[3 * m + 1];
        int x = coords[3 * m + 2];
        g_map[(b * BEV_H + y) * BEV_W + x] = m + 1;
    }
}

// ---------------------------------------------------------------------------
// Kernel 2: dense gather via channel-major smem transpose.
// Block owns 128 consecutive raveled cells (never straddles a batch:
// 214272 % 128 == 0).
//  P1: coalesced map read + self-clean.
//  P2: 8 iters; warp covers 8 slots x 4 quads -> LDG.128 hits 8 rows x 64B
//      aligned chunks (8 lines/instr); stage to s_f[c*SST + s] (4 scalar STS,
//      2-way banks). Empty cells (uniform per 4-lane group) stage zeros.
//  P3: 8 iters; lane l handles slots 4l..4l+3 of channel c = w*8+j:
//      LDS.128 (conflict-free) + STG.128 (512B/warp contiguous).
__global__ __launch_bounds__(256) void gather_kernel(
    const float* __restrict__ feat, float* __restrict__ out) {
    __shared__ int   s_map[CELLS_PB];
    __shared__ float s_f[NC * SST];           // 33,792 B

    const int t    = threadIdx.x;
    const int base = blockIdx.x * CELLS_PB;

    // Phase 1: coalesced map read + self-clean
    if (t < CELLS_PB) {
        int pid = g_map[base + t];
        s_map[t] = pid;
        if (pid) g_map[base + t] = 0;
    }
    __syncthreads();

    // Phase 2: coalesced feature loads -> channel-major smem
#pragma unroll
    for (int it = 0; it < 8; ++it) {
        const int s = ((it & 1) << 6) + (t >> 2);     // 0..127
        const int q = (t & 3) + ((it >> 1) << 2);     // 0..15
        const int pid = s_map[s];
        float4 v = make_float4(0.f, 0.f, 0.f, 0.f);
        if (pid)
            v = *reinterpret_cast<const float4*>(
                    feat + (size_t)(pid - 1) * NC + 4 * q);
        const int c = 4 * q;
        s_f[(c + 0) * SST + s] = v.x;
        s_f[(c + 1) * SST + s] = v.y;
        s_f[(c + 2) * SST + s] = v.z;
        s_f[(c + 3) * SST + s] = v.w;
    }
    __syncthreads();

    // Phase 3: vector transpose out of smem, fully coalesced stores
    const int w = t >> 5;
    const int l = t & 31;
    const int b = base / HW;                          // constant per block
    float* outb = out + (size_t)b * NC * HW + (base - b * HW);
#pragma unroll
    for (int j = 0; j < 8; ++j) {
        const int c = w * 8 + j;
        const float4 v = *reinterpret_cast<const float4*>(&s_f[c * SST + 4 * l]);
        *reinterpret_cast<float4*>(&outb[(size_t)c * HW + 4 * l]) = v;
    }
}

// ---------------------------------------------------------------------------
extern "C" void kernel_launch(void* const* d_in, const int* in_sizes, int n_in,
                              void* d_out, int out_size) {
    const int*   coords = (const int*)d_in[0];    // (M, 3) int32
    const float* feat   = (const float*)d_in[1];  // (M, 64) float32
    float*       out    = (float*)d_out;          // (4, 64, 496, 432) float32
    const int M = in_sizes[0] / 3;

    scatter_idx_kernel<<<(M + 255) / 256, 256>>>(coords, M);
    gather_kernel<<<NBLK, 256>>>(feat, out);
}

// round 6
// speedup vs baseline: 1.4000x; 1.2431x over previous
#include <cuda_runtime.h>
#include <stdint.h>

// PointPillars BEV scatter: (M,3) coords + (M,64) features -> (B,64,496,432)
#define BEV_H   496
#define BEV_W   432
#define NB      4
#define NC      64
#define HW      (BEV_H * BEV_W)        // 214272 cells per batch image
#define HW4     (HW / 4)               // 53568 float4-cells per batch image
#define NCELL4  (NB * HW4)             // 214272 float4-cells total
#define CPT     8                      // channels per thread
#define CPB     32                     // float4-cells per block (block = 32*8 = 256)
#define NBLK    (NCELL4 / CPB)         // 6696 blocks, exact (53568 % 32 == 0)

// Inverse map: raveled cell -> pillar index + 1 (0 = empty). 3.43 MB.
// SELF-CLEANING: zero at module load; gather zeroes occupied entries after all
// channel groups have read them -> all-zero again at the end of every call.
__device__ int g_map[NB * HW];

// ---------------------------------------------------------------------------
// Kernel 1: scatter pillar index+1 into the map (coords are collision-free).
__global__ void scatter_idx_kernel(const int* __restrict__ coords, int M) {
    int m = blockIdx.x * blockDim.x + threadIdx.x;
    if (m < M) {
        int b = coords[3 * m + 0];
        int y = coords[3 * m + 1];
        int x = coords[3 * m + 2];
        g_map[(b * BEV_H + y) * BEV_W + x] = m + 1;
    }
}

// ---------------------------------------------------------------------------
// Kernel 2: direct register-transpose gather, channel-split 8 ways.
// t&31 -> float4-cell within block span, t>>5 -> channel group (8 ch).
// Flat addressing: float4-cell i covers g_map[4i..4i+3]; block never
// straddles a batch (HW4 % CPB == 0), so b is uniform per block.
// Per thread: 1 int4 map load, <=8 float4 feature loads (only ~0.6 of the 4
// pillars occupied on average), 8 float4 streaming stores (512 B/warp).
__global__ __launch_bounds__(256) void gather_kernel(
    const float* __restrict__ feat, float* __restrict__ out) {
    const int t    = threadIdx.x;
    const int cg   = t >> 5;                       // 0..7
    const int cell = blockIdx.x * CPB + (t & 31);  // global float4-cell

    int4* mpp = reinterpret_cast<int4*>(&g_map[4 * cell]);
    const int4 mp = *mpp;
    __syncthreads();                               // all 8 cgroups have read
    if (cg == 0 && (mp.x | mp.y | mp.z | mp.w)) {
        *mpp = make_int4(0, 0, 0, 0);              // self-clean for next call
    }

    const int pi[4] = { mp.x, mp.y, mp.z, mp.w };
    float4 v[4][2];                                // [pillar][2 quads of 4 ch]
#pragma unroll
    for (int p = 0; p < 4; ++p) {
        if (pi[p]) {
            const float4* fp = reinterpret_cast<const float4*>(
                feat + (size_t)(pi[p] - 1) * NC + cg * CPT);
            v[p][0] = fp[0];
            v[p][1] = fp[1];
        } else {
            v[p][0] = v[p][1] = make_float4(0.f, 0.f, 0.f, 0.f);
        }
    }

    const int b = (4 * cell) / HW;                 // uniform per block
    float* outp = out + ((size_t)(b * NC + cg * CPT)) * HW + (4 * cell - b * HW);
    const size_t cs = (size_t)HW;
#pragma unroll
    for (int q = 0; q < 2; ++q) {
        __stcs(reinterpret_cast<float4*>(outp),
               make_float4(v[0][q].x, v[1][q].x, v[2][q].x, v[3][q].x));
        outp += cs;
        __stcs(reinterpret_cast<float4*>(outp),
               make_float4(v[0][q].y, v[1][q].y, v[2][q].y, v[3][q].y));
        outp += cs;
        __stcs(reinterpret_cast<float4*>(outp),
               make_float4(v[0][q].z, v[1][q].z, v[2][q].z, v[3][q].z));
        outp += cs;
        __stcs(reinterpret_cast<float4*>(outp),
               make_float4(v[0][q].w, v[1][q].w, v[2][q].w, v[3][q].w));
        outp += cs;
    }
}

// ---------------------------------------------------------------------------
extern "C" void kernel_launch(void* const* d_in, const int* in_sizes, int n_in,
                              void* d_out, int out_size) {
    const int*   coords = (const int*)d_in[0];    // (M, 3) int32
    const float* feat   = (const float*)d_in[1];  // (M, 64) float32
    float*       out    = (float*)d_out;          // (4, 64, 496, 432) float32
    const int M = in_sizes[0] / 3;

    scatter_idx_kernel<<<(M + 255) / 256, 256>>>(coords, M);
    gather_kernel<<<NBLK, 256>>>(feat, out);
}

// round 9
// speedup vs baseline: 1.4105x; 1.0075x over previous
#include <cuda_runtime.h>
#include <stdint.h>

// PointPillars BEV scatter: (M,3) coords + (M,64) features -> (B,64,496,432)
#define BEV_H   496
#define BEV_W   432
#define NB      4
#define NC      64
#define HW      (BEV_H * BEV_W)        // 214272 cells per batch image
#define HW4     (HW / 4)               // 53568 float4-cells per batch image
#define NCELL4  (NB * HW4)             // 214272 float4-cells total
#define CPT     16                     // channels per thread
#define NCG     (NC / CPT)             // 4 channel groups
#define CPB     64                     // float4-cells per block (block = 64*4 = 256)
#define NBLK    (NCELL4 / CPB)         // 3348 blocks, exact (53568 % 64 == 0)

// Inverse map: raveled cell -> pillar index + 1 (0 = empty). 3.43 MB.
// SELF-CLEANING: zero at module load; gather zeroes occupied entries after all
// channel groups have read them -> all-zero again at the end of every call.
__device__ int g_map[NB * HW];

// ---------------------------------------------------------------------------
// Kernel 1: scatter pillar index+1 into the map (coords are collision-free).
__global__ void scatter_idx_kernel(const int* __restrict__ coords, int M) {
    int m = blockIdx.x * blockDim.x + threadIdx.x;
    if (m < M) {
        int b = coords[3 * m + 0];
        int y = coords[3 * m + 1];
        int x = coords[3 * m + 2];
        g_map[(b * BEV_H + y) * BEV_W + x] = m + 1;
    }
}

// ---------------------------------------------------------------------------
// Kernel 2: direct register-transpose gather, channel-split 4 ways.
// t&63 -> float4-cell within block span, t>>6 -> channel group (16 ch).
// Flat addressing: float4-cell i covers g_map[4i..4i+3]; blocks never
// straddle a batch (HW4 % CPB == 0), so b is uniform per block.
// Per thread: 1 int4 map load, <=16 float4 feature loads (~0.57 of the 4
// pillars occupied on average), 16 float4 streaming stores (512 B/warp each).
__global__ __launch_bounds__(256) void gather_kernel(
    const float* __restrict__ feat, float* __restrict__ out) {
    const int t    = threadIdx.x;
    const int cg   = t >> 6;                       // 0..3
    const int cell = blockIdx.x * CPB + (t & 63);  // global float4-cell

    int4* mpp = reinterpret_cast<int4*>(&g_map[4 * cell]);
    const int4 mp = *mpp;
    __syncthreads();                               // all 4 cgroups have read
    if (cg == 0 && (mp.x | mp.y | mp.z | mp.w)) {
        *mpp = make_int4(0, 0, 0, 0);              // self-clean for next call
    }

    const int pi[4] = { mp.x, mp.y, mp.z, mp.w };
    float4 v[4][4];                                // [pillar][4 quads of 4 ch]
#pragma unroll
    for (int p = 0; p < 4; ++p) {
        if (pi[p]) {
            const float4* fp = reinterpret_cast<const float4*>(
                feat + (size_t)(pi[p] - 1) * NC + cg * CPT);
            v[p][0] = fp[0]; v[p][1] = fp[1]; v[p][2] = fp[2]; v[p][3] = fp[3];
        } else {
            v[p][0] = v[p][1] = v[p][2] = v[p][3] = make_float4(0.f, 0.f, 0.f, 0.f);
        }
    }

    const int b = (4 * cell) / HW;                 // uniform per block
    float* outp = out + ((size_t)(b * NC + cg * CPT)) * HW + (4 * cell - b * HW);
    const size_t cs = (size_t)HW;
#pragma unroll
    for (int q = 0; q < 4; ++q) {
        __stcs(reinterpret_cast<float4*>(outp),
               make_float4(v[0][q].x, v[1][q].x, v[2][q].x, v[3][q].x));
        outp += cs;
        __stcs(reinterpret_cast<float4*>(outp),
               make_float4(v[0][q].y, v[1][q].y, v[2][q].y, v[3][q].y));
        outp += cs;
        __stcs(reinterpret_cast<float4*>(outp),
               make_float4(v[0][q].z, v[1][q].z, v[2][q].z, v[3][q].z));
        outp += cs;
        __stcs(reinterpret_cast<float4*>(outp),
               make_float4(v[0][q].w, v[1][q].w, v[2][q].w, v[3][q].w));
        outp += cs;
    }
}

// ---------------------------------------------------------------------------
extern "C" void kernel_launch(void* const* d_in, const int* in_sizes, int n_in,
                              void* d_out, int out_size) {
    const int*   coords = (const int*)d_in[0];    // (M, 3) int32
    const float* feat   = (const float*)d_in[1];  // (M, 64) float32
    float*       out    = (float*)d_out;          // (4, 64, 496, 432) float32
    const int M = in_sizes[0] / 3;

    scatter_idx_kernel<<<(M + 255) / 256, 256>>>(coords, M);
    gather_kernel<<<NBLK, 256>>>(feat, out);
}